// round 9
// baseline (speedup 1.0000x reference)
#include <cuda_runtime.h>
#include <cuda_bf16.h>

// Problem: ClassCaps_86182813762001   (R8 resubmit — R0..R7 never ran: broker timeouts)
// votes[b,h,w,i,o,m,p] = sum_n poses[b,h,w,i,m,n] * weight[i,o,n,p]  (+ coord add)
// out = concat(votes.flatten(), activations.flatten())
//
// B=64 H=14 W=14 CI=32 A=4 CO=10
// votes f4 = 16,056,320 ; acts f4 = 100,352 ; total = 16,156,672 (all %32 == 0)

static constexpr unsigned NVOTE_F4 = 16056320u;
static constexpr unsigned NACT_F4  = 100352u;
static constexpr unsigned NTOT_F4  = NVOTE_F4 + NACT_F4;

__device__ __forceinline__ float4 shfl_xor_f4(float4 v, int lanemask) {
    float4 r;
    r.x = __shfl_xor_sync(0xffffffffu, v.x, lanemask);
    r.y = __shfl_xor_sync(0xffffffffu, v.y, lanemask);
    r.z = __shfl_xor_sync(0xffffffffu, v.z, lanemask);
    r.w = __shfl_xor_sync(0xffffffffu, v.w, lanemask);
    return r;
}

__global__ __launch_bounds__(256) void classcaps_kernel(
    const float4* __restrict__ poses4,   // [B*H*W*CI*4] float4 (rows m, 4 floats n)
    const float4* __restrict__ acts4,    // [B*H*W*CI/4] float4
    const float4* __restrict__ wgt4,     // [CI*CO*4] float4 (rows n, 4 floats p)
    const float*  __restrict__ xv,       // [H*W]
    const float*  __restrict__ yv,       // [H*W]
    float4*       __restrict__ out4)
{
    unsigned q = blockIdx.x * blockDim.x + threadIdx.x;   // grid exact; no oob threads
    if (q >= NVOTE_F4) {
        // tail: verbatim activations copy (whole warps; boundary is 32-aligned)
        out4[q] = acts4[q - NVOTE_F4];
        return;
    }

    // q = ((bhwi*10 + o)*4 + m)   -- 32-bit unsigned math only
    unsigned m = q & 3u;
    unsigned t = q >> 2;                 // bhwi*10 + o  (lanes 0-3 of a group share t)
    unsigned bhwi = t / 10u;             // div-by-const -> IMAD.HI + shift
    unsigned o = t - bhwi * 10u;
    unsigned hwi = bhwi % 6272u;         // (h*14 + w)*32 + i
    unsigned i  = hwi & 31u;
    unsigned hw = hwi >> 5;              // h*14 + w

    // This lane's pose row m (scalars indexed by n). 1-2 distinct bhwi per warp
    // -> coalescer dedups to ~1 line wavefront.
    float4 pr = poses4[(size_t)bhwi * 4u + m];

    // Coord value hoisted early so its latency overlaps the shuffle waits.
    // m==0 -> xv[hw], m==1 -> yv[hw], else 0.
    float coord = 0.0f;
    if (m < 2u) coord = (m == 0u) ? xv[hw] : yv[hw];

    // Weight tile [i][o] is 4 rows; lane m loads ONLY row m (one LDG.128 spanning
    // 8 consecutive 64B tiles per warp), then two butterfly rounds rebuild all rows.
    float4 own = wgt4[(size_t)(i * 10u + o) * 4u + m];   // w[m]
    float4 a = shfl_xor_f4(own, 1);                      // w[m^1]
    float4 b = shfl_xor_f4(own, 2);                      // w[m^2]
    float4 c = shfl_xor_f4(a,   2);                      // w[m^3]

    // Pose scalars permuted to match: s_k = pr[m^k]  (verified for all m)
    bool b0 = (m & 1u) != 0u;
    bool b1 = (m & 2u) != 0u;
    float c0 = b0 ? pr.y : pr.x;
    float c1 = b0 ? pr.x : pr.y;
    float c2 = b0 ? pr.w : pr.z;
    float c3 = b0 ? pr.z : pr.w;
    float s0 = b1 ? c2 : c0;       // pr[m]
    float s1 = b1 ? c3 : c1;       // pr[m^1]
    float s2 = b1 ? c0 : c2;       // pr[m^2]
    float s3 = b1 ? c1 : c3;       // pr[m^3]

    // r[p] = sum_n pr[n] * w[n][p]  (reassociated over the xor ordering)
    float4 r;
    r.x = s0 * own.x + s1 * a.x + s2 * b.x + s3 * c.x;
    r.y = s0 * own.y + s1 * a.y + s2 * b.y + s3 * c.y;
    r.z = s0 * own.z + s1 * a.z + s2 * b.z + s3 * c.z;
    r.w = (s0 * own.w + s1 * a.w + s2 * b.w + s3 * c.w) + coord;

    out4[q] = r;
}

extern "C" void kernel_launch(void* const* d_in, const int* in_sizes, int n_in,
                              void* d_out, int out_size)
{
    const float4* poses4 = (const float4*)d_in[0];
    const float4* acts4  = (const float4*)d_in[1];
    const float4* wgt4   = (const float4*)d_in[2];
    const float*  xv     = (const float*)d_in[3];
    const float*  yv     = (const float*)d_in[4];
    float4* out4 = (float4*)d_out;

    const unsigned threads = 256u;
    const unsigned blocks = (NTOT_F4 + threads - 1u) / threads;  // exact: NTOT_F4 % 256 == 0
    classcaps_kernel<<<blocks, threads>>>(poses4, acts4, wgt4, xv, yv, out4);
}

// round 15
// speedup vs baseline: 1.3389x; 1.3389x over previous
#include <cuda_runtime.h>
#include <cuda_bf16.h>

// Problem: ClassCaps_86182813762001   (R14 resubmit of R9 — R9..R13 broker timeouts)
// Design: smem weight tile (80B-padded, conflict-free), no shuffles,
// persistent one-wave grid-stride loop.
// votes[b,h,w,i,o,m,p] = sum_n poses[b,h,w,i,m,n] * weight[i,o,n,p]  (+ coord add)
// out = concat(votes.flatten(), activations.flatten())
//
// B=64 H=14 W=14 CI=32 A=4 CO=10
// votes f4 = 16,056,320 ; acts f4 = 100,352 ; total = 16,156,672 (all %32 == 0)

static constexpr unsigned NVOTE_F4 = 16056320u;
static constexpr unsigned NACT_F4  = 100352u;
static constexpr unsigned NTOT_F4  = NVOTE_F4 + NACT_F4;

static constexpr unsigned NTHREADS = 256u;
static constexpr unsigned NBLOCKS  = 1184u;              // 148 SMs x 8 blocks = one wave
static constexpr unsigned STRIDE   = NBLOCKS * NTHREADS; // 303,104 (%4==0 -> m loop-invariant; %32==0 -> warp-uniform branches)

// Weight tiles: 320 tiles (i*10+o), 4 float4 rows each. Padded to 5 float4 (80 B)
// per tile so a warp's 8 groups hit 8 distinct banks ({0,20,8,28,16,4,24,12} words
// mod 32) -> conflict-free LDS.128 with 4-lane broadcast.
static constexpr unsigned WTILES = 320u;

__global__ __launch_bounds__(256) void classcaps_kernel(
    const float4* __restrict__ poses4,   // [B*H*W*CI*4] float4 (rows m, 4 floats n)
    const float4* __restrict__ acts4,    // [B*H*W*CI/4] float4
    const float4* __restrict__ wgt4,     // [CI*CO*4] float4 (rows n, 4 floats p)
    const float*  __restrict__ xv,       // [H*W]
    const float*  __restrict__ yv,       // [H*W]
    float4*       __restrict__ out4)
{
    __shared__ float4 wsmem[WTILES * 5u];   // 25,600 B

    // Fill: 1280 float4 / 256 threads = 5 each (amortized over ~53 outputs/thread)
    for (unsigned idx = threadIdx.x; idx < WTILES * 4u; idx += NTHREADS) {
        unsigned tile = idx >> 2, n = idx & 3u;
        wsmem[tile * 5u + n] = wgt4[idx];
    }
    __syncthreads();

    unsigned q0 = blockIdx.x * NTHREADS + threadIdx.x;
    unsigned m  = q0 & 3u;                 // invariant: STRIDE % 4 == 0
    const bool mlt2 = (m < 2u);
    const bool m_is0 = (m == 0u);

    for (unsigned q = q0; q < NTOT_F4; q += STRIDE) {
        if (q >= NVOTE_F4) {
            // tail: verbatim activations copy (warp-uniform: boundary %32==0)
            out4[q] = acts4[q - NVOTE_F4];
            continue;
        }

        // q = ((bhwi*10 + o)*4 + m)
        unsigned t = q >> 2;
        unsigned bhwi = t / 10u;             // div-by-const -> IMAD.HI
        unsigned o = t - bhwi * 10u;
        unsigned hwi = bhwi % 6272u;         // (h*14 + w)*32 + i
        unsigned i  = hwi & 31u;
        unsigned hw = hwi >> 5;              // h*14 + w

        // Streaming pose row m (coalescer dedups the 10x o-reuse across the warp)
        float4 pr = poses4[(size_t)bhwi * 4u + m];

        // Coord hoisted so its latency overlaps the LDS waits.
        float coord = 0.0f;
        if (mlt2) coord = m_is0 ? xv[hw] : yv[hw];

        // Weight tile rows in natural order from smem (4 independent LDS.128,
        // broadcast across the 4 lanes of each group, conflict-free via 80B pad)
        const float4* w = &wsmem[(i * 10u + o) * 5u];
        float4 w0 = w[0], w1 = w[1], w2 = w[2], w3 = w[3];

        float4 r;
        r.x = pr.x * w0.x + pr.y * w1.x + pr.z * w2.x + pr.w * w3.x;
        r.y = pr.x * w0.y + pr.y * w1.y + pr.z * w2.y + pr.w * w3.y;
        r.z = pr.x * w0.z + pr.y * w1.z + pr.z * w2.z + pr.w * w3.z;
        r.w = (pr.x * w0.w + pr.y * w1.w + pr.z * w2.w + pr.w * w3.w) + coord;

        out4[q] = r;
    }
}

extern "C" void kernel_launch(void* const* d_in, const int* in_sizes, int n_in,
                              void* d_out, int out_size)
{
    const float4* poses4 = (const float4*)d_in[0];
    const float4* acts4  = (const float4*)d_in[1];
    const float4* wgt4   = (const float4*)d_in[2];
    const float*  xv     = (const float*)d_in[3];
    const float*  yv     = (const float*)d_in[4];
    float4* out4 = (float4*)d_out;

    classcaps_kernel<<<NBLOCKS, NTHREADS>>>(poses4, acts4, wgt4, xv, yv, out4);
}